// round 5
// baseline (speedup 1.0000x reference)
#include <cuda_runtime.h>
#include <cstdint>
#include <math.h>

#define SEQ   4096
#define EMB   256
#define H     256
#define G4    1024   // 4*H
#define NTAGS 32

// ---------------- scratch (device globals: no allocation allowed) ----------
__device__ float g_gx[2][SEQ][G4];     // input projections per direction
__device__ float g_hs[SEQ][2 * H];     // concatenated BiLSTM hidden states
__device__ float g_em[SEQ][NTAGS];     // emissions

__device__ __forceinline__ unsigned smem_u32(const void* p) {
    return (unsigned)__cvta_generic_to_shared(p);
}

#define CLUSTER_SYNC_ASM() do { \
    asm volatile("barrier.cluster.arrive.aligned;" ::: "memory"); \
    asm volatile("barrier.cluster.wait.aligned;"   ::: "memory"); \
} while (0)

// cluster-scope acquire wait on local mbarrier, phase-parity style
__device__ __forceinline__ void mbar_wait_cl(unsigned addr, unsigned parity) {
    unsigned done;
    asm volatile(
        "{\n\t.reg .pred p;\n\t"
        "mbarrier.try_wait.parity.acquire.cluster.shared::cta.b64 p, [%1], %2;\n\t"
        "selp.b32 %0, 1, 0, p;\n\t}"
        : "=r"(done) : "r"(addr), "r"(parity) : "memory");
    if (!done) {
        asm volatile(
            "{\n\t.reg .pred P1;\n\t"
            "W_%=:\n\t"
            "mbarrier.try_wait.parity.acquire.cluster.shared::cta.b64 P1, [%0], %1, 0x989680;\n\t"
            "@P1 bra.uni D_%=;\n\t"
            "bra.uni W_%=;\n\t"
            "D_%=:\n\t}"
            :: "r"(addr), "r"(parity) : "memory");
    }
}

// ============================================================================
// Kernel A: gx[d][t][r] = emb_d[t] . w_ih_d[r] + b_ih[r] + b_hh[r]
// ============================================================================
__global__ void gx_kernel(const float* __restrict__ embed,
                          const float* __restrict__ w_ih_f,
                          const float* __restrict__ b_ih_f,
                          const float* __restrict__ b_hh_f,
                          const float* __restrict__ w_ih_b,
                          const float* __restrict__ b_ih_b,
                          const float* __restrict__ b_hh_b,
                          const int*   __restrict__ x)
{
    const int dir = blockIdx.z;
    const float* w_ih = dir ? w_ih_b : w_ih_f;
    const float* b_ih = dir ? b_ih_b : b_ih_f;
    const float* b_hh = dir ? b_hh_b : b_hh_f;

    __shared__ float As[64][33];
    __shared__ float Bs[64][33];
    __shared__ int   toks[64];

    const int tid = threadIdx.x;
    const int t0 = blockIdx.x * 64;
    const int r0 = blockIdx.y * 64;

    if (tid < 64) {
        int t = t0 + tid;
        int p = dir ? (SEQ - 1 - t) : t;
        toks[tid] = x[p];
    }
    __syncthreads();

    const int tx = tid & 15, ty = tid >> 4;
    float c[4][4] = {};

    for (int k0 = 0; k0 < EMB; k0 += 32) {
        for (int i = tid; i < 64 * 32; i += 256) {
            int row = i >> 5, k = i & 31;
            As[row][k] = embed[(size_t)toks[row] * EMB + k0 + k];
        }
        for (int i = tid; i < 64 * 32; i += 256) {
            int row = i >> 5, k = i & 31;
            Bs[row][k] = w_ih[(size_t)(r0 + row) * EMB + k0 + k];
        }
        __syncthreads();
        #pragma unroll
        for (int kk = 0; kk < 32; kk++) {
            float a[4], b[4];
            #pragma unroll
            for (int u = 0; u < 4; u++) a[u] = As[ty * 4 + u][kk];
            #pragma unroll
            for (int v = 0; v < 4; v++) b[v] = Bs[tx * 4 + v][kk];
            #pragma unroll
            for (int u = 0; u < 4; u++)
                #pragma unroll
                for (int v = 0; v < 4; v++)
                    c[u][v] += a[u] * b[v];
        }
        __syncthreads();
    }

    #pragma unroll
    for (int u = 0; u < 4; u++) {
        int t = t0 + ty * 4 + u;
        #pragma unroll
        for (int v = 0; v < 4; v++) {
            int r = r0 + tx * 4 + v;
            g_gx[dir][t][r] = c[u][v] + b_ih[r] + b_hh[r];
        }
    }
}

// ============================================================================
// Kernel B: sequential BiLSTM recurrence (2 clusters of 8 CTAs).
// Lane layout per warp: (j_local[1] | gate[2] | slice[2]) -> no block barrier
// in the hot loop: slice-reduce = 2 shfl_xor, gate-combine = 4 shfl_idx.
// W_hh slice in registers as f32x2 pairs (fma.rn.f32x2).
// Cross-CTA h broadcast: st.shared::cluster + double-buffered DSMEM mbarriers
// (arrive.release.cluster / try_wait.parity.acquire.cluster).
// ============================================================================
#define HPAD 68   // 64-float slice + 4 pad floats (conflict-free quad access)

__global__ void __cluster_dims__(8, 1, 1) __launch_bounds__(512, 1)
lstm_kernel(const float* __restrict__ w_hh_f, const float* __restrict__ w_hh_b)
{
    __shared__ __align__(16) float shp[2][4 * HPAD];   // padded h, double buffer
    __shared__ __align__(8) unsigned long long mbar[2];

    const int tid = threadIdx.x;
    const int dir = blockIdx.x >> 3;
    unsigned rank;
    asm("mov.u32 %0, %%cluster_ctarank;" : "=r"(rank));
    const int j0 = (int)rank * 32;

    const int wz   = tid >> 5;            // warp 0..15
    const int l    = tid & 31;
    const int jl   = (l >> 4) & 1;        // hidden-within-warp
    const int gate = (l >> 2) & 3;        // i,f,g,o
    const int s    = l & 3;               // K slice (64 wide)
    const int jg   = wz * 2 + jl;         // hidden unit within CTA (0..31)
    const int jglob = j0 + jg;            // global hidden unit (0..255)
    const int row  = gate * H + jglob;    // gate row in W_hh

    const float* __restrict__ w_hh = dir ? w_hh_b : w_hh_f;

    // ---- weights into registers as packed f32x2 pairs ----
    unsigned long long w2[32];
    {
        const ulonglong2* wv =
            (const ulonglong2*)(w_hh + (size_t)row * H + s * 64);
        #pragma unroll
        for (int q = 0; q < 16; q++) {
            ulonglong2 v = wv[q];
            w2[2 * q] = v.x; w2[2 * q + 1] = v.y;
        }
    }

    // ---- init smem ----
    for (int i = tid; i < 2 * 4 * HPAD; i += 512) ((float*)shp)[i] = 0.f;
    if (tid == 0) {
        unsigned b0 = smem_u32(&mbar[0]), b1 = smem_u32(&mbar[1]);
        asm volatile("mbarrier.init.shared.b64 [%0], 256;" :: "r"(b0) : "memory");
        asm volatile("mbarrier.init.shared.b64 [%0], 256;" :: "r"(b1) : "memory");
    }

    const bool leader = ((l & 15) == 0);   // 2 per warp, 32 per CTA
    const int slice_j = jglob >> 6, off_j = jglob & 63;
    unsigned hraddr[2][8];
    if (leader) {
        #pragma unroll
        for (int b = 0; b < 2; b++) {
            unsigned la = smem_u32(&shp[b][slice_j * HPAD + off_j]);
            #pragma unroll
            for (int cc = 0; cc < 8; cc++)
                asm("mapa.shared::cluster.u32 %0, %1, %2;"
                    : "=r"(hraddr[b][cc]) : "r"(la), "r"(cc));
        }
    }
    unsigned bar_la[2] = { smem_u32(&mbar[0]), smem_u32(&mbar[1]) };

    CLUSTER_SYNC_ASM();   // zeros + mbarrier init visible cluster-wide

    float cst = 0.f;
    const float* __restrict__ gx_base = &g_gx[dir][0][0];
    const float L2E = 1.4426950408889634f;

    for (int step = 0; step < SEQ; step++) {
        // prefetch gx (independent of h) before the wait
        float gxv = __ldg(gx_base + (size_t)step * G4 + row);

        if (step > 0) {
            int pb = (step - 1) & 1;
            unsigned pa = ((unsigned)(step - 1) >> 1) & 1u;
            mbar_wait_cl(bar_la[pb], pa);
        }
        const int rb = step & 1, wb = rb ^ 1;

        // ---- matvec over this lane's 64-wide slice (f32x2 FFMA) ----
        const ulonglong2* hv = (const ulonglong2*)&shp[rb][s * HPAD];
        unsigned long long acc0 = 0ull, acc1 = 0ull;
        #pragma unroll
        for (int q = 0; q < 16; q++) {
            ulonglong2 h2 = hv[q];
            asm("fma.rn.f32x2 %0, %1, %2, %0;"
                : "+l"(acc0) : "l"(w2[2 * q]),     "l"(h2.x));
            asm("fma.rn.f32x2 %0, %1, %2, %0;"
                : "+l"(acc1) : "l"(w2[2 * q + 1]), "l"(h2.y));
        }
        float lo0, hi0, lo1, hi1;
        asm("mov.b64 {%0,%1}, %2;" : "=f"(lo0), "=f"(hi0) : "l"(acc0));
        asm("mov.b64 {%0,%1}, %2;" : "=f"(lo1), "=f"(hi1) : "l"(acc1));
        float p = (lo0 + hi0) + (lo1 + hi1);
        p += __shfl_xor_sync(~0u, p, 1);
        p += __shfl_xor_sync(~0u, p, 2);      // sum over 4 slices
        float xg = p + gxv;

        // ---- activation: sigmoid for i,f,o ; tanh for g ----
        float kk = (gate == 2) ? 2.f : 1.f;
        float e, r;
        asm("ex2.approx.f32 %0, %1;" : "=f"(e) : "f"(-L2E * kk * xg));
        asm("rcp.approx.f32 %0, %1;" : "=f"(r) : "f"(1.f + e));
        float act = (gate == 2) ? (2.f * r - 1.f) : r;

        const int base = l & 16;
        float ia = __shfl_sync(~0u, act, base + 0);
        float fa = __shfl_sync(~0u, act, base + 4);
        float ga = __shfl_sync(~0u, act, base + 8);
        float oa = __shfl_sync(~0u, act, base + 12);
        cst = fa * cst + ia * ga;
        float e2, r2;
        asm("ex2.approx.f32 %0, %1;" : "=f"(e2) : "f"(-2.f * L2E * cst));
        asm("rcp.approx.f32 %0, %1;" : "=f"(r2) : "f"(1.f + e2));
        float h = oa * (2.f * r2 - 1.f);

        if (leader) {
            #pragma unroll
            for (int cc = 0; cc < 8; cc++)
                asm volatile("st.shared::cluster.f32 [%0], %1;"
                             :: "r"(hraddr[wb][cc]), "f"(h));
            int pos = dir ? (SEQ - 1 - step) : step;
            g_hs[pos][dir * H + jglob] = h;
            unsigned bl = bar_la[step & 1];
            #pragma unroll
            for (int cc = 0; cc < 8; cc++) {
                unsigned ra;
                asm("mapa.shared::cluster.u32 %0, %1, %2;"
                    : "=r"(ra) : "r"(bl), "r"(cc));
                asm volatile(
                    "mbarrier.arrive.release.cluster.shared::cluster.b64 _, [%0];"
                    :: "r"(ra) : "memory");
            }
        }
    }
    CLUSTER_SYNC_ASM();   // keep peer smem alive until all stores landed
}

// ============================================================================
// Kernel C: emissions em[t][k] = hs[t] . w_lin[k] + b_lin[k]
// ============================================================================
__global__ void emis_kernel(const float* __restrict__ w_lin,
                            const float* __restrict__ b_lin)
{
    __shared__ float hsm[512];
    __shared__ float redc[512];
    const int t = blockIdx.x, tid = threadIdx.x;
    hsm[tid] = g_hs[t][tid];
    __syncthreads();

    const int k = tid & 31, sl = tid >> 5;
    float p = 0.f;
    #pragma unroll
    for (int m = 0; m < 32; m++)
        p += hsm[sl * 32 + m] * __ldg(&w_lin[k * 512 + sl * 32 + m]);
    redc[sl * 32 + k] = p;
    __syncthreads();

    if (tid < 32) {
        float sum = b_lin[tid];
        #pragma unroll
        for (int s2 = 0; s2 < 16; s2++) sum += redc[s2 * 32 + tid];
        g_em[t][tid] = sum;
    }
}

// ============================================================================
// Kernel D: CRF NLL. 256 threads: 8 lanes per tag, 4 exp terms per lane,
// 3-level shfl reduce, exp2/lg2 fast path, alpha[0]-shift (no max pass).
// ============================================================================
__global__ void __launch_bounds__(256, 1)
crf_kernel(const float* __restrict__ trans,
           const float* __restrict__ start_trans,
           const float* __restrict__ end_trans,
           const int*   __restrict__ y,
           float* __restrict__ out)
{
    __shared__ __align__(16) float alpha[2][NTAGS];
    __shared__ float s_num;
    __shared__ float s_red[8];

    const int tid = threadIdx.x;
    const int lane = tid & 31, warp = tid >> 5;
    const int j   = tid >> 3;   // tag this thread contributes to
    const int sub = tid & 7;    // which group of 4 source tags

    const float L2E = 1.4426950408889634f;
    const float LN2 = 0.6931471805599453f;

    // trans[i][j] for i = sub*4 .. sub*4+3, pre-scaled by log2(e)
    float t0 = trans[(sub * 4 + 0) * NTAGS + j] * L2E;
    float t1 = trans[(sub * 4 + 1) * NTAGS + j] * L2E;
    float t2 = trans[(sub * 4 + 2) * NTAGS + j] * L2E;
    float t3 = trans[(sub * 4 + 3) * NTAGS + j] * L2E;

    // ---- gold path score (numerator) ----
    float part = 0.f;
    for (int t = tid; t < SEQ; t += 256) {
        int yt = y[t];
        part += g_em[t][yt];
        if (t > 0) part += trans[y[t - 1] * NTAGS + yt];
    }
    #pragma unroll
    for (int o = 16; o; o >>= 1) part += __shfl_xor_sync(~0u, part, o);
    if (lane == 0) s_red[warp] = part;
    __syncthreads();
    if (tid == 0) {
        float num = start_trans[y[0]] + end_trans[y[SEQ - 1]];
        #pragma unroll
        for (int wv = 0; wv < 8; wv++) num += s_red[wv];
        s_num = num;
    }
    if (tid < NTAGS) alpha[0][tid] = start_trans[tid] + g_em[0][tid];
    __syncthreads();

    // ---- forward algorithm ----
    float emv = g_em[1][j];   // prefetch step 1
    for (int t = 1; t < SEQ; t++) {
        const int rp = (t - 1) & 1, wp = t & 1;
        float4 a4 = *(const float4*)&alpha[rp][sub * 4];
        float ref = alpha[rp][0];
        float rb2 = -ref * L2E;
        float e0, e1, e2, e3;
        asm("ex2.approx.f32 %0, %1;" : "=f"(e0) : "f"(fmaf(a4.x, L2E, t0 + rb2)));
        asm("ex2.approx.f32 %0, %1;" : "=f"(e1) : "f"(fmaf(a4.y, L2E, t1 + rb2)));
        asm("ex2.approx.f32 %0, %1;" : "=f"(e2) : "f"(fmaf(a4.z, L2E, t2 + rb2)));
        asm("ex2.approx.f32 %0, %1;" : "=f"(e3) : "f"(fmaf(a4.w, L2E, t3 + rb2)));
        float ssum = (e0 + e1) + (e2 + e3);
        ssum += __shfl_xor_sync(~0u, ssum, 1);
        ssum += __shfl_xor_sync(~0u, ssum, 2);
        ssum += __shfl_xor_sync(~0u, ssum, 4);
        float em_cur = emv;
        if (t + 1 < SEQ) emv = g_em[t + 1][j];
        if (sub == 0) {
            float lg;
            asm("lg2.approx.f32 %0, %1;" : "=f"(lg) : "f"(ssum));
            alpha[wp][j] = ref + lg * LN2 + em_cur;
        }
        __syncthreads();
    }

    if (warp == 0) {
        float v = alpha[(SEQ - 1) & 1][lane] + end_trans[lane];
        float m = v;
        #pragma unroll
        for (int o = 16; o; o >>= 1) m = fmaxf(m, __shfl_xor_sync(~0u, m, o));
        float e = __expf(v - m);
        #pragma unroll
        for (int o = 16; o; o >>= 1) e += __shfl_xor_sync(~0u, e, o);
        if (lane == 0) out[0] = (m + __logf(e)) - s_num;
    }
}

// ============================================================================
extern "C" void kernel_launch(void* const* d_in, const int* in_sizes, int n_in,
                              void* d_out, int out_size)
{
    const float* embed       = (const float*)d_in[0];
    const float* w_ih_f      = (const float*)d_in[1];
    const float* w_hh_f      = (const float*)d_in[2];
    const float* b_ih_f      = (const float*)d_in[3];
    const float* b_hh_f      = (const float*)d_in[4];
    const float* w_ih_b      = (const float*)d_in[5];
    const float* w_hh_b      = (const float*)d_in[6];
    const float* b_ih_b      = (const float*)d_in[7];
    const float* b_hh_b      = (const float*)d_in[8];
    const float* w_lin       = (const float*)d_in[9];
    const float* b_lin       = (const float*)d_in[10];
    const float* trans       = (const float*)d_in[11];
    const float* start_trans = (const float*)d_in[12];
    const float* end_trans   = (const float*)d_in[13];
    const int*   x           = (const int*)d_in[14];
    const int*   y           = (const int*)d_in[15];

    dim3 gA(SEQ / 64, G4 / 64, 2);
    gx_kernel<<<gA, 256>>>(embed, w_ih_f, b_ih_f, b_hh_f,
                           w_ih_b, b_ih_b, b_hh_b, x);
    lstm_kernel<<<16, 512>>>(w_hh_f, w_hh_b);
    emis_kernel<<<SEQ, 512>>>(w_lin, b_lin);
    crf_kernel<<<1, 256>>>(trans, start_trans, end_trans, y, (float*)d_out);
}

// round 7
// speedup vs baseline: 1.4046x; 1.4046x over previous
#include <cuda_runtime.h>
#include <cstdint>
#include <math.h>

#define SEQ   4096
#define EMB   256
#define H     256
#define G4    1024   // 4*H
#define NTAGS 32

// ---------------- scratch (device globals: no allocation allowed) ----------
__device__ float g_gx[2][SEQ][G4];     // input projections per direction
__device__ float g_hs[SEQ][2 * H];     // concatenated BiLSTM hidden states
__device__ float g_em[SEQ][NTAGS];     // emissions

__device__ __forceinline__ unsigned smem_u32(const void* p) {
    return (unsigned)__cvta_generic_to_shared(p);
}

#define CLUSTER_ARRIVE() \
    asm volatile("barrier.cluster.arrive.aligned;" ::: "memory")
#define CLUSTER_WAIT() \
    asm volatile("barrier.cluster.wait.aligned;"   ::: "memory")
#define CLUSTER_SYNC_ASM() do { CLUSTER_ARRIVE(); CLUSTER_WAIT(); } while (0)

// ============================================================================
// Kernel A: gx[d][t][r] = emb_d[t] . w_ih_d[r] + b_ih[r] + b_hh[r]
// ============================================================================
__global__ void gx_kernel(const float* __restrict__ embed,
                          const float* __restrict__ w_ih_f,
                          const float* __restrict__ b_ih_f,
                          const float* __restrict__ b_hh_f,
                          const float* __restrict__ w_ih_b,
                          const float* __restrict__ b_ih_b,
                          const float* __restrict__ b_hh_b,
                          const int*   __restrict__ x)
{
    const int dir = blockIdx.z;
    const float* w_ih = dir ? w_ih_b : w_ih_f;
    const float* b_ih = dir ? b_ih_b : b_ih_f;
    const float* b_hh = dir ? b_hh_b : b_hh_f;

    __shared__ float As[64][33];
    __shared__ float Bs[64][33];
    __shared__ int   toks[64];

    const int tid = threadIdx.x;
    const int t0 = blockIdx.x * 64;
    const int r0 = blockIdx.y * 64;

    if (tid < 64) {
        int t = t0 + tid;
        int p = dir ? (SEQ - 1 - t) : t;
        toks[tid] = x[p];
    }
    __syncthreads();

    const int tx = tid & 15, ty = tid >> 4;
    float c[4][4] = {};

    for (int k0 = 0; k0 < EMB; k0 += 32) {
        for (int i = tid; i < 64 * 32; i += 256) {
            int row = i >> 5, k = i & 31;
            As[row][k] = embed[(size_t)toks[row] * EMB + k0 + k];
        }
        for (int i = tid; i < 64 * 32; i += 256) {
            int row = i >> 5, k = i & 31;
            Bs[row][k] = w_ih[(size_t)(r0 + row) * EMB + k0 + k];
        }
        __syncthreads();
        #pragma unroll
        for (int kk = 0; kk < 32; kk++) {
            float a[4], b[4];
            #pragma unroll
            for (int u = 0; u < 4; u++) a[u] = As[ty * 4 + u][kk];
            #pragma unroll
            for (int v = 0; v < 4; v++) b[v] = Bs[tx * 4 + v][kk];
            #pragma unroll
            for (int u = 0; u < 4; u++)
                #pragma unroll
                for (int v = 0; v < 4; v++)
                    c[u][v] += a[u] * b[v];
        }
        __syncthreads();
    }

    #pragma unroll
    for (int u = 0; u < 4; u++) {
        int t = t0 + ty * 4 + u;
        #pragma unroll
        for (int v = 0; v < 4; v++) {
            int r = r0 + tx * 4 + v;
            g_gx[dir][t][r] = c[u][v] + b_ih[r] + b_hh[r];
        }
    }
}

// ============================================================================
// Kernel B: sequential BiLSTM recurrence (2 clusters of 8 CTAs).
// Lane layout per warp: (j_local[1] | gate[2] | slice[2]) -> no block barrier
// in the hot loop: slice-reduce = 2 shfl_xor, gate-combine = 4 shfl_idx.
// W_hh slice in registers as f32x2 pairs (fma.rn.f32x2).
// Cross-CTA h broadcast: st.shared::cluster, ordered by the HARDWARE cluster
// barrier (arrive at end of step / wait at top of next step — the arrive's
// release semantics publish the remote stores).  Software mbarriers were a
// 2.5x regression here: 256 remote arrives/step serialize at the destination
// smem atomic unit, vs one aggregated HW barrier.
// ============================================================================
#define HPAD 68   // 64-float slice + 4 pad floats (16B-aligned: 68*4=272=17*16)

__global__ void __cluster_dims__(8, 1, 1) __launch_bounds__(512, 1)
lstm_kernel(const float* __restrict__ w_hh_f, const float* __restrict__ w_hh_b)
{
    __shared__ __align__(16) float shp[2][4 * HPAD];   // padded h, double buffer

    const int tid = threadIdx.x;
    const int dir = blockIdx.x >> 3;
    unsigned rank;
    asm("mov.u32 %0, %%cluster_ctarank;" : "=r"(rank));
    const int j0 = (int)rank * 32;

    const int wz   = tid >> 5;            // warp 0..15
    const int l    = tid & 31;
    const int jl   = (l >> 4) & 1;        // hidden-within-warp
    const int gate = (l >> 2) & 3;        // i,f,g,o
    const int s    = l & 3;               // K slice (64 wide)
    const int jg   = wz * 2 + jl;         // hidden unit within CTA (0..31)
    const int jglob = j0 + jg;            // global hidden unit (0..255)
    const int row  = gate * H + jglob;    // gate row in W_hh

    const float* __restrict__ w_hh = dir ? w_hh_b : w_hh_f;

    // ---- weights into registers as packed f32x2 pairs ----
    unsigned long long w2[32];
    {
        const ulonglong2* wv =
            (const ulonglong2*)(w_hh + (size_t)row * H + s * 64);
        #pragma unroll
        for (int q = 0; q < 16; q++) {
            ulonglong2 v = wv[q];
            w2[2 * q] = v.x; w2[2 * q + 1] = v.y;
        }
    }

    // ---- init smem ----
    for (int i = tid; i < 2 * 4 * HPAD; i += 512) ((float*)shp)[i] = 0.f;

    const bool leader = ((l & 15) == 0);   // 2 per warp, 32 per CTA
    const int slice_j = jglob >> 6, off_j = jglob & 63;
    unsigned hraddr[2][8];
    if (leader) {
        #pragma unroll
        for (int b = 0; b < 2; b++) {
            unsigned la = smem_u32(&shp[b][slice_j * HPAD + off_j]);
            #pragma unroll
            for (int cc = 0; cc < 8; cc++)
                asm("mapa.shared::cluster.u32 %0, %1, %2;"
                    : "=r"(hraddr[b][cc]) : "r"(la), "r"(cc));
        }
    }

    CLUSTER_SYNC_ASM();   // zeros visible cluster-wide

    float cst = 0.f;
    const float* __restrict__ gx_base = &g_gx[dir][0][0];
    const float L2E = 1.4426950408889634f;

    for (int step = 0; step < SEQ; step++) {
        // prefetch gx (independent of h) BEFORE the barrier wait
        float gxv = __ldg(gx_base + (size_t)step * G4 + row);

        if (step > 0) CLUSTER_WAIT();   // h_{t-1} remote stores published
        const int rb = step & 1, wb = rb ^ 1;

        // ---- matvec over this lane's 64-wide slice (f32x2 FFMA) ----
        const ulonglong2* hv = (const ulonglong2*)&shp[rb][s * HPAD];
        unsigned long long acc0 = 0ull, acc1 = 0ull;
        #pragma unroll
        for (int q = 0; q < 16; q++) {
            ulonglong2 h2 = hv[q];
            asm("fma.rn.f32x2 %0, %1, %2, %0;"
                : "+l"(acc0) : "l"(w2[2 * q]),     "l"(h2.x));
            asm("fma.rn.f32x2 %0, %1, %2, %0;"
                : "+l"(acc1) : "l"(w2[2 * q + 1]), "l"(h2.y));
        }
        float lo0, hi0, lo1, hi1;
        asm("mov.b64 {%0,%1}, %2;" : "=f"(lo0), "=f"(hi0) : "l"(acc0));
        asm("mov.b64 {%0,%1}, %2;" : "=f"(lo1), "=f"(hi1) : "l"(acc1));
        float p = (lo0 + hi0) + (lo1 + hi1);
        p += __shfl_xor_sync(~0u, p, 1);
        p += __shfl_xor_sync(~0u, p, 2);      // sum over 4 slices
        float xg = p + gxv;

        // ---- activation: sigmoid for i,f,o ; tanh for g ----
        float kk = (gate == 2) ? 2.f : 1.f;
        float e, r;
        asm("ex2.approx.f32 %0, %1;" : "=f"(e) : "f"(-L2E * kk * xg));
        asm("rcp.approx.f32 %0, %1;" : "=f"(r) : "f"(1.f + e));
        float act = (gate == 2) ? (2.f * r - 1.f) : r;

        const int base = l & 16;
        float ia = __shfl_sync(~0u, act, base + 0);
        float fa = __shfl_sync(~0u, act, base + 4);
        float ga = __shfl_sync(~0u, act, base + 8);
        float oa = __shfl_sync(~0u, act, base + 12);
        cst = fa * cst + ia * ga;
        float e2, r2;
        asm("ex2.approx.f32 %0, %1;" : "=f"(e2) : "f"(-2.f * L2E * cst));
        asm("rcp.approx.f32 %0, %1;" : "=f"(r2) : "f"(1.f + e2));
        float h = oa * (2.f * r2 - 1.f);

        if (leader) {
            #pragma unroll
            for (int cc = 0; cc < 8; cc++)
                asm volatile("st.shared::cluster.f32 [%0], %1;"
                             :: "r"(hraddr[wb][cc]), "f"(h));
            int pos = dir ? (SEQ - 1 - step) : step;
            g_hs[pos][dir * H + jglob] = h;
        }
        CLUSTER_ARRIVE();   // release: publishes this step's remote h stores
    }
    CLUSTER_WAIT();         // match final arrives; smem alive until all landed
}

// ============================================================================
// Kernel C: emissions em[t][k] = hs[t] . w_lin[k] + b_lin[k]
// ============================================================================
__global__ void emis_kernel(const float* __restrict__ w_lin,
                            const float* __restrict__ b_lin)
{
    __shared__ float hsm[512];
    __shared__ float redc[512];
    const int t = blockIdx.x, tid = threadIdx.x;
    hsm[tid] = g_hs[t][tid];
    __syncthreads();

    const int k = tid & 31, sl = tid >> 5;
    float p = 0.f;
    #pragma unroll
    for (int m = 0; m < 32; m++)
        p += hsm[sl * 32 + m] * __ldg(&w_lin[k * 512 + sl * 32 + m]);
    redc[sl * 32 + k] = p;
    __syncthreads();

    if (tid < 32) {
        float sum = b_lin[tid];
        #pragma unroll
        for (int s2 = 0; s2 < 16; s2++) sum += redc[s2 * 32 + tid];
        g_em[t][tid] = sum;
    }
}

// ============================================================================
// Kernel D: CRF NLL. 256 threads: 8 lanes per tag, 4 exp terms per lane,
// 3-level shfl reduce, exp2/lg2 fast path, alpha[0]-shift (no max pass).
// ============================================================================
__global__ void __launch_bounds__(256, 1)
crf_kernel(const float* __restrict__ trans,
           const float* __restrict__ start_trans,
           const float* __restrict__ end_trans,
           const int*   __restrict__ y,
           float* __restrict__ out)
{
    __shared__ __align__(16) float alpha[2][NTAGS];
    __shared__ float s_num;
    __shared__ float s_red[8];

    const int tid = threadIdx.x;
    const int lane = tid & 31, warp = tid >> 5;
    const int j   = tid >> 3;   // tag this thread contributes to
    const int sub = tid & 7;    // which group of 4 source tags

    const float L2E = 1.4426950408889634f;
    const float LN2 = 0.6931471805599453f;

    // trans[i][j] for i = sub*4 .. sub*4+3, pre-scaled by log2(e)
    float t0 = trans[(sub * 4 + 0) * NTAGS + j] * L2E;
    float t1 = trans[(sub * 4 + 1) * NTAGS + j] * L2E;
    float t2 = trans[(sub * 4 + 2) * NTAGS + j] * L2E;
    float t3 = trans[(sub * 4 + 3) * NTAGS + j] * L2E;

    // ---- gold path score (numerator) ----
    float part = 0.f;
    for (int t = tid; t < SEQ; t += 256) {
        int yt = y[t];
        part += g_em[t][yt];
        if (t > 0) part += trans[y[t - 1] * NTAGS + yt];
    }
    #pragma unroll
    for (int o = 16; o; o >>= 1) part += __shfl_xor_sync(~0u, part, o);
    if (lane == 0) s_red[warp] = part;
    __syncthreads();
    if (tid == 0) {
        float num = start_trans[y[0]] + end_trans[y[SEQ - 1]];
        #pragma unroll
        for (int wv = 0; wv < 8; wv++) num += s_red[wv];
        s_num = num;
    }
    if (tid < NTAGS) alpha[0][tid] = start_trans[tid] + g_em[0][tid];
    __syncthreads();

    // ---- forward algorithm ----
    float emv = g_em[1][j];   // prefetch step 1
    for (int t = 1; t < SEQ; t++) {
        const int rp = (t - 1) & 1, wp = t & 1;
        float4 a4 = *(const float4*)&alpha[rp][sub * 4];
        float ref = alpha[rp][0];
        float rb2 = -ref * L2E;
        float e0, e1, e2, e3;
        asm("ex2.approx.f32 %0, %1;" : "=f"(e0) : "f"(fmaf(a4.x, L2E, t0 + rb2)));
        asm("ex2.approx.f32 %0, %1;" : "=f"(e1) : "f"(fmaf(a4.y, L2E, t1 + rb2)));
        asm("ex2.approx.f32 %0, %1;" : "=f"(e2) : "f"(fmaf(a4.z, L2E, t2 + rb2)));
        asm("ex2.approx.f32 %0, %1;" : "=f"(e3) : "f"(fmaf(a4.w, L2E, t3 + rb2)));
        float ssum = (e0 + e1) + (e2 + e3);
        ssum += __shfl_xor_sync(~0u, ssum, 1);
        ssum += __shfl_xor_sync(~0u, ssum, 2);
        ssum += __shfl_xor_sync(~0u, ssum, 4);
        float em_cur = emv;
        if (t + 1 < SEQ) emv = g_em[t + 1][j];
        if (sub == 0) {
            float lg;
            asm("lg2.approx.f32 %0, %1;" : "=f"(lg) : "f"(ssum));
            alpha[wp][j] = ref + lg * LN2 + em_cur;
        }
        __syncthreads();
    }

    if (warp == 0) {
        float v = alpha[(SEQ - 1) & 1][lane] + end_trans[lane];
        float m = v;
        #pragma unroll
        for (int o = 16; o; o >>= 1) m = fmaxf(m, __shfl_xor_sync(~0u, m, o));
        float e = __expf(v - m);
        #pragma unroll
        for (int o = 16; o; o >>= 1) e += __shfl_xor_sync(~0u, e, o);
        if (lane == 0) out[0] = (m + __logf(e)) - s_num;
    }
}

// ============================================================================
extern "C" void kernel_launch(void* const* d_in, const int* in_sizes, int n_in,
                              void* d_out, int out_size)
{
    const float* embed       = (const float*)d_in[0];
    const float* w_ih_f      = (const float*)d_in[1];
    const float* w_hh_f      = (const float*)d_in[2];
    const float* b_ih_f      = (const float*)d_in[3];
    const float* b_hh_f      = (const float*)d_in[4];
    const float* w_ih_b      = (const float*)d_in[5];
    const float* w_hh_b      = (const float*)d_in[6];
    const float* b_ih_b      = (const float*)d_in[7];
    const float* b_hh_b      = (const float*)d_in[8];
    const float* w_lin       = (const float*)d_in[9];
    const float* b_lin       = (const float*)d_in[10];
    const float* trans       = (const float*)d_in[11];
    const float* start_trans = (const float*)d_in[12];
    const float* end_trans   = (const float*)d_in[13];
    const int*   x           = (const int*)d_in[14];
    const int*   y           = (const int*)d_in[15];

    dim3 gA(SEQ / 64, G4 / 64, 2);
    gx_kernel<<<gA, 256>>>(embed, w_ih_f, b_ih_f, b_hh_f,
                           w_ih_b, b_ih_b, b_hh_b, x);
    lstm_kernel<<<16, 512>>>(w_hh_f, w_hh_b);
    emis_kernel<<<SEQ, 512>>>(w_lin, b_lin);
    crf_kernel<<<1, 256>>>(trans, start_trans, end_trans, y, (float*)d_out);
}

// round 8
// speedup vs baseline: 2.9199x; 2.0788x over previous
#include <cuda_runtime.h>
#include <cstdint>
#include <math.h>

#define SEQ   4096
#define EMB   256
#define H     256
#define G4    1024   // 4*H
#define NTAGS 32

// ---------------- scratch (device globals: no allocation allowed) ----------
__device__ float g_gx[2][SEQ][G4];     // input projections per direction
__device__ float g_hs[SEQ][2 * H];     // concatenated BiLSTM hidden states
__device__ float g_em[SEQ][NTAGS];     // emissions

__device__ __forceinline__ unsigned smem_u32(const void* p) {
    return (unsigned)__cvta_generic_to_shared(p);
}

#define CLUSTER_ARRIVE() \
    asm volatile("barrier.cluster.arrive.aligned;" ::: "memory")
#define CLUSTER_WAIT() \
    asm volatile("barrier.cluster.wait.aligned;"   ::: "memory")
#define CLUSTER_SYNC_ASM() do { CLUSTER_ARRIVE(); CLUSTER_WAIT(); } while (0)

// ============================================================================
// Kernel A: gx[d][t][r] = emb_d[t] . w_ih_d[r] + b_ih[r] + b_hh[r]
// ============================================================================
__global__ void gx_kernel(const float* __restrict__ embed,
                          const float* __restrict__ w_ih_f,
                          const float* __restrict__ b_ih_f,
                          const float* __restrict__ b_hh_f,
                          const float* __restrict__ w_ih_b,
                          const float* __restrict__ b_ih_b,
                          const float* __restrict__ b_hh_b,
                          const int*   __restrict__ x)
{
    const int dir = blockIdx.z;
    const float* w_ih = dir ? w_ih_b : w_ih_f;
    const float* b_ih = dir ? b_ih_b : b_ih_f;
    const float* b_hh = dir ? b_hh_b : b_hh_f;

    __shared__ float As[64][33];
    __shared__ float Bs[64][33];
    __shared__ int   toks[64];

    const int tid = threadIdx.x;
    const int t0 = blockIdx.x * 64;
    const int r0 = blockIdx.y * 64;

    if (tid < 64) {
        int t = t0 + tid;
        int p = dir ? (SEQ - 1 - t) : t;
        toks[tid] = x[p];
    }
    __syncthreads();

    const int tx = tid & 15, ty = tid >> 4;
    float c[4][4] = {};

    for (int k0 = 0; k0 < EMB; k0 += 32) {
        for (int i = tid; i < 64 * 32; i += 256) {
            int row = i >> 5, k = i & 31;
            As[row][k] = embed[(size_t)toks[row] * EMB + k0 + k];
        }
        for (int i = tid; i < 64 * 32; i += 256) {
            int row = i >> 5, k = i & 31;
            Bs[row][k] = w_ih[(size_t)(r0 + row) * EMB + k0 + k];
        }
        __syncthreads();
        #pragma unroll
        for (int kk = 0; kk < 32; kk++) {
            float a[4], b[4];
            #pragma unroll
            for (int u = 0; u < 4; u++) a[u] = As[ty * 4 + u][kk];
            #pragma unroll
            for (int v = 0; v < 4; v++) b[v] = Bs[tx * 4 + v][kk];
            #pragma unroll
            for (int u = 0; u < 4; u++)
                #pragma unroll
                for (int v = 0; v < 4; v++)
                    c[u][v] += a[u] * b[v];
        }
        __syncthreads();
    }

    #pragma unroll
    for (int u = 0; u < 4; u++) {
        int t = t0 + ty * 4 + u;
        #pragma unroll
        for (int v = 0; v < 4; v++) {
            int r = r0 + tx * 4 + v;
            g_gx[dir][t][r] = c[u][v] + b_ih[r] + b_hh[r];
        }
    }
}

// ============================================================================
// Kernel B: sequential BiLSTM recurrence (2 clusters of 8 CTAs).
// Round-2 structure (proven fastest): warp-uniform K slice, smem reduction,
// 32-thread tail — NO shuffles and only one warp of MUFU in the hot loop
// (the per-thread shuffle/MUFU layout of r5/r7 oversubscribed the XU pipe).
// Deltas vs round 2:
//   * f32x2 FFMA matvec (halves FMA issue slots)
//   * remote-addr double buffer in REGISTERS (r2 indexed raddr[wb][] -> LDL)
//   * split cluster arrive/wait so gx prefetch overlaps the barrier wait
//   * ex2/rcp activations in the tail
// ============================================================================
__global__ void __cluster_dims__(8, 1, 1) __launch_bounds__(512, 1)
lstm_kernel(const float* __restrict__ w_hh_f, const float* __restrict__ w_hh_b)
{
    __shared__ __align__(16) float sh_h[2][256];   // double-buffered h
    __shared__ float red[512];

    const int tid = threadIdx.x;
    const int dir = blockIdx.x >> 3;
    unsigned rank;
    asm("mov.u32 %0, %%cluster_ctarank;" : "=r"(rank));
    const int j0 = (int)rank * 32;

    const float* __restrict__ w_hh = dir ? w_hh_b : w_hh_f;

    // thread -> (gate row, K-slice).  Warp lanes share the slice s, so the
    // sh_h reads below are pure broadcasts (conflict-free).
    const int g    = ((tid >> 7) << 5) | (tid & 31);  // 0..127 local gate id
    const int s    = (tid >> 5) & 3;                  // 0..3  K slice
    const int gate = g >> 5;                          // i,f,g,o
    const int j    = g & 31;                          // hidden index within CTA
    const int row  = gate * H + j0 + j;               // global gate row

    // ---- weights into registers as packed f32x2 pairs ----
    unsigned long long w2[32];
    {
        const ulonglong2* wv =
            (const ulonglong2*)(w_hh + (size_t)row * H + s * 64);
        #pragma unroll
        for (int q = 0; q < 16; q++) {
            ulonglong2 v = wv[q];
            w2[2 * q] = v.x; w2[2 * q + 1] = v.y;
        }
    }

    if (tid < 256) { sh_h[0][tid] = 0.f; sh_h[1][tid] = 0.f; }

    // remote h addresses, kept in two SEPARATE register arrays (constant
    // indices only after unroll -> no local-memory spill)
    unsigned raddr0[8], raddr1[8];
    if (tid < 32) {
        unsigned la0 = smem_u32(&sh_h[0][j0 + tid]);
        unsigned la1 = smem_u32(&sh_h[1][j0 + tid]);
        #pragma unroll
        for (int cc = 0; cc < 8; cc++) {
            asm("mapa.shared::cluster.u32 %0, %1, %2;"
                : "=r"(raddr0[cc]) : "r"(la0), "r"(cc));
            asm("mapa.shared::cluster.u32 %0, %1, %2;"
                : "=r"(raddr1[cc]) : "r"(la1), "r"(cc));
        }
    }

    CLUSTER_SYNC_ASM();   // zeros visible cluster-wide

    float cstate = 0.f;
    const float* __restrict__ gx_base = &g_gx[dir][0][0];
    const float L2E = 1.4426950408889634f;

    for (int step = 0; step < SEQ; step++) {
        // prefetch gx[step] (independent of h) BEFORE the barrier wait
        float gxv0 = 0.f, gxv1 = 0.f, gxv2 = 0.f, gxv3 = 0.f;
        if (tid < 32) {
            const float* p = gx_base + (size_t)step * G4 + j0 + tid;
            gxv0 = __ldg(p + 0 * H);
            gxv1 = __ldg(p + 1 * H);
            gxv2 = __ldg(p + 2 * H);
            gxv3 = __ldg(p + 3 * H);
        }

        if (step > 0) CLUSTER_WAIT();   // h_{t-1} remote stores published
        const int rb = step & 1, wb = rb ^ 1;

        // ---- phase 1: partial dot over this thread's 64-wide K slice ----
        const ulonglong2* hv = (const ulonglong2*)&sh_h[rb][s * 64];
        unsigned long long acc0 = 0ull, acc1 = 0ull;
        #pragma unroll
        for (int q = 0; q < 16; q++) {
            ulonglong2 h2 = hv[q];
            asm("fma.rn.f32x2 %0, %1, %2, %0;"
                : "+l"(acc0) : "l"(w2[2 * q]),     "l"(h2.x));
            asm("fma.rn.f32x2 %0, %1, %2, %0;"
                : "+l"(acc1) : "l"(w2[2 * q + 1]), "l"(h2.y));
        }
        float lo0, hi0, lo1, hi1;
        asm("mov.b64 {%0,%1}, %2;" : "=f"(lo0), "=f"(hi0) : "l"(acc0));
        asm("mov.b64 {%0,%1}, %2;" : "=f"(lo1), "=f"(hi1) : "l"(acc1));
        red[s * 128 + g] = (lo0 + hi0) + (lo1 + hi1);
        __syncthreads();

        // ---- phase 2: 32 owner threads finish gates, cell update, bcast ----
        if (tid < 32) {
            float gi = gxv0, gf = gxv1, gg = gxv2, go = gxv3;
            #pragma unroll
            for (int sl = 0; sl < 4; sl++) {
                gi += red[sl * 128 + 0 * 32 + tid];
                gf += red[sl * 128 + 1 * 32 + tid];
                gg += red[sl * 128 + 2 * 32 + tid];
                go += red[sl * 128 + 3 * 32 + tid];
            }
            float ei, ef, eg, eo, iv, fv, gv, ov;
            asm("ex2.approx.f32 %0, %1;" : "=f"(ei) : "f"(-L2E * gi));
            asm("ex2.approx.f32 %0, %1;" : "=f"(ef) : "f"(-L2E * gf));
            asm("ex2.approx.f32 %0, %1;" : "=f"(eg) : "f"(-2.f * L2E * gg));
            asm("ex2.approx.f32 %0, %1;" : "=f"(eo) : "f"(-L2E * go));
            asm("rcp.approx.f32 %0, %1;" : "=f"(iv) : "f"(1.f + ei));
            asm("rcp.approx.f32 %0, %1;" : "=f"(fv) : "f"(1.f + ef));
            asm("rcp.approx.f32 %0, %1;" : "=f"(gv) : "f"(1.f + eg));
            asm("rcp.approx.f32 %0, %1;" : "=f"(ov) : "f"(1.f + eo));
            gv = 2.f * gv - 1.f;                     // tanh(gg)
            cstate = fv * cstate + iv * gv;
            float ec, rc;
            asm("ex2.approx.f32 %0, %1;" : "=f"(ec) : "f"(-2.f * L2E * cstate));
            asm("rcp.approx.f32 %0, %1;" : "=f"(rc) : "f"(1.f + ec));
            float h = ov * (2.f * rc - 1.f);

            #pragma unroll
            for (int cc = 0; cc < 8; cc++) {
                unsigned ad = wb ? raddr1[cc] : raddr0[cc];
                asm volatile("st.shared::cluster.f32 [%0], %1;"
                             :: "r"(ad), "f"(h));
            }
            int pos = dir ? (SEQ - 1 - step) : step;
            g_hs[pos][dir * H + j0 + tid] = h;
        }
        CLUSTER_ARRIVE();   // release: publishes this step's remote h stores
    }
    CLUSTER_WAIT();         // match final arrives; smem alive until all landed
}

// ============================================================================
// Kernel C: emissions em[t][k] = hs[t] . w_lin[k] + b_lin[k]
// ============================================================================
__global__ void emis_kernel(const float* __restrict__ w_lin,
                            const float* __restrict__ b_lin)
{
    __shared__ float hsm[512];
    __shared__ float redc[512];
    const int t = blockIdx.x, tid = threadIdx.x;
    hsm[tid] = g_hs[t][tid];
    __syncthreads();

    const int k = tid & 31, sl = tid >> 5;
    float p = 0.f;
    #pragma unroll
    for (int m = 0; m < 32; m++)
        p += hsm[sl * 32 + m] * __ldg(&w_lin[k * 512 + sl * 32 + m]);
    redc[sl * 32 + k] = p;
    __syncthreads();

    if (tid < 32) {
        float sum = b_lin[tid];
        #pragma unroll
        for (int s2 = 0; s2 < 16; s2++) sum += redc[s2 * 32 + tid];
        g_em[t][tid] = sum;
    }
}

// ============================================================================
// Kernel D: CRF NLL. 256 threads: 8 lanes per tag, 4 exp terms per lane,
// 3-level shfl reduce, exp2/lg2 fast path, alpha[0]-shift (no max pass).
// ============================================================================
__global__ void __launch_bounds__(256, 1)
crf_kernel(const float* __restrict__ trans,
           const float* __restrict__ start_trans,
           const float* __restrict__ end_trans,
           const int*   __restrict__ y,
           float* __restrict__ out)
{
    __shared__ __align__(16) float alpha[2][NTAGS];
    __shared__ float s_num;
    __shared__ float s_red[8];

    const int tid = threadIdx.x;
    const int lane = tid & 31, warp = tid >> 5;
    const int j   = tid >> 3;   // tag this thread contributes to
    const int sub = tid & 7;    // which group of 4 source tags

    const float L2E = 1.4426950408889634f;
    const float LN2 = 0.6931471805599453f;

    // trans[i][j] for i = sub*4 .. sub*4+3, pre-scaled by log2(e)
    float t0 = trans[(sub * 4 + 0) * NTAGS + j] * L2E;
    float t1 = trans[(sub * 4 + 1) * NTAGS + j] * L2E;
    float t2 = trans[(sub * 4 + 2) * NTAGS + j] * L2E;
    float t3 = trans[(sub * 4 + 3) * NTAGS + j] * L2E;

    // ---- gold path score (numerator) ----
    float part = 0.f;
    for (int t = tid; t < SEQ; t += 256) {
        int yt = y[t];
        part += g_em[t][yt];
        if (t > 0) part += trans[y[t - 1] * NTAGS + yt];
    }
    #pragma unroll
    for (int o = 16; o; o >>= 1) part += __shfl_xor_sync(~0u, part, o);
    if (lane == 0) s_red[warp] = part;
    __syncthreads();
    if (tid == 0) {
        float num = start_trans[y[0]] + end_trans[y[SEQ - 1]];
        #pragma unroll
        for (int wv = 0; wv < 8; wv++) num += s_red[wv];
        s_num = num;
    }
    if (tid < NTAGS) alpha[0][tid] = start_trans[tid] + g_em[0][tid];
    __syncthreads();

    // ---- forward algorithm ----
    float emv = g_em[1][j];   // prefetch step 1
    for (int t = 1; t < SEQ; t++) {
        const int rp = (t - 1) & 1, wp = t & 1;
        float4 a4 = *(const float4*)&alpha[rp][sub * 4];
        float ref = alpha[rp][0];
        float rb2 = -ref * L2E;
        float e0, e1, e2, e3;
        asm("ex2.approx.f32 %0, %1;" : "=f"(e0) : "f"(fmaf(a4.x, L2E, t0 + rb2)));
        asm("ex2.approx.f32 %0, %1;" : "=f"(e1) : "f"(fmaf(a4.y, L2E, t1 + rb2)));
        asm("ex2.approx.f32 %0, %1;" : "=f"(e2) : "f"(fmaf(a4.z, L2E, t2 + rb2)));
        asm("ex2.approx.f32 %0, %1;" : "=f"(e3) : "f"(fmaf(a4.w, L2E, t3 + rb2)));
        float ssum = (e0 + e1) + (e2 + e3);
        ssum += __shfl_xor_sync(~0u, ssum, 1);
        ssum += __shfl_xor_sync(~0u, ssum, 2);
        ssum += __shfl_xor_sync(~0u, ssum, 4);
        float em_cur = emv;
        if (t + 1 < SEQ) emv = g_em[t + 1][j];
        if (sub == 0) {
            float lg;
            asm("lg2.approx.f32 %0, %1;" : "=f"(lg) : "f"(ssum));
            alpha[wp][j] = ref + lg * LN2 + em_cur;
        }
        __syncthreads();
    }

    if (warp == 0) {
        float v = alpha[(SEQ - 1) & 1][lane] + end_trans[lane];
        float m = v;
        #pragma unroll
        for (int o = 16; o; o >>= 1) m = fmaxf(m, __shfl_xor_sync(~0u, m, o));
        float e = __expf(v - m);
        #pragma unroll
        for (int o = 16; o; o >>= 1) e += __shfl_xor_sync(~0u, e, o);
        if (lane == 0) out[0] = (m + __logf(e)) - s_num;
    }
}

// ============================================================================
extern "C" void kernel_launch(void* const* d_in, const int* in_sizes, int n_in,
                              void* d_out, int out_size)
{
    const float* embed       = (const float*)d_in[0];
    const float* w_ih_f      = (const float*)d_in[1];
    const float* w_hh_f      = (const float*)d_in[2];
    const float* b_ih_f      = (const float*)d_in[3];
    const float* b_hh_f      = (const float*)d_in[4];
    const float* w_ih_b      = (const float*)d_in[5];
    const float* w_hh_b      = (const float*)d_in[6];
    const float* b_ih_b      = (const float*)d_in[7];
    const float* b_hh_b      = (const float*)d_in[8];
    const float* w_lin       = (const float*)d_in[9];
    const float* b_lin       = (const float*)d_in[10];
    const float* trans       = (const float*)d_in[11];
    const float* start_trans = (const float*)d_in[12];
    const float* end_trans   = (const float*)d_in[13];
    const int*   x           = (const int*)d_in[14];
    const int*   y           = (const int*)d_in[15];

    dim3 gA(SEQ / 64, G4 / 64, 2);
    gx_kernel<<<gA, 256>>>(embed, w_ih_f, b_ih_f, b_hh_f,
                           w_ih_b, b_ih_b, b_hh_b, x);
    lstm_kernel<<<16, 512>>>(w_hh_f, w_hh_b);
    emis_kernel<<<SEQ, 512>>>(w_lin, b_lin);
    crf_kernel<<<1, 256>>>(trans, start_trans, end_trans, y, (float*)d_out);
}